// round 6
// baseline (speedup 1.0000x reference)
#include <cuda_runtime.h>

// Problem constants
#define B_ 8
#define N_ 2048
#define F_ 128
#define M_ (B_*N_)          // 16384 total rows
#define LAYERS_ 2
#define NSPLIT_ 16
#define SLOPE_ 0.1f
#define INV_NM1_ (1.0f/2047.0f)
#define PADT_ 132           // XsT row pad: 132*4 bytes = multiple of 16 (float4-safe)

typedef unsigned long long ull;

// Scratch (device globals; no cudaMalloc allowed)
__device__ float g_w1[M_*F_];
__device__ float g_w2[M_*F_];
__device__ float g_diag[M_];
__device__ float g_Spart[B_*NSPLIT_*F_*F_];
__device__ float g_S[B_*F_*F_];

__device__ __forceinline__ float lrelu(float v) { return v >= 0.f ? v : SLOPE_*v; }

// ---- packed fp32x2 helpers (sm_100+: one FFMA2 issue = 2 FMAs) ----
__device__ __forceinline__ ull dup2(float a) {
    ull r; asm("mov.b64 %0, {%1, %1};" : "=l"(r) : "f"(a)); return r;
}
__device__ __forceinline__ ull ffma2(ull a, ull b, ull c) {
    ull d; asm("fma.rn.f32x2 %0, %1, %2, %3;" : "=l"(d) : "l"(a), "l"(b), "l"(c));
    return d;
}
__device__ __forceinline__ float2 unpk(ull v) {
    float2 f; asm("mov.b64 {%0, %1}, %2;" : "=f"(f.x), "=f"(f.y) : "l"(v)); return f;
}

// ---------------------------------------------------------------------------
// Shared tile helpers. A transposed: XsT[k][row] (pad PADT_). B: Ws[k][col].
// 256 threads: tx = tid&15 (8 cols), ty = tid>>4 (8 rows).
// ---------------------------------------------------------------------------
__device__ __forceinline__ void load_XT_chunk(
    const float* __restrict__ X, int row0, int c, int tid, float (*XsT)[PADT_])
{
    #pragma unroll
    for (int i = 0; i < 4; ++i) {
        int f4 = tid + i*256;
        int r  = f4 >> 3;             // 0..127
        int kq = (f4 & 7) << 2;       // 0..28
        float4 v = *(const float4*)&X[(size_t)(row0 + r)*F_ + c*32 + kq];
        XsT[kq+0][r] = v.x; XsT[kq+1][r] = v.y;
        XsT[kq+2][r] = v.z; XsT[kq+3][r] = v.w;
    }
}

__device__ __forceinline__ void load_W_chunk(
    const float* __restrict__ W, int c, int tid, float (*Ws)[128])
{
    #pragma unroll
    for (int i = 0; i < 4; ++i) {
        int f4 = tid + i*256;
        int r  = f4 >> 5;
        int q  = (f4 & 31) << 2;
        *(float4*)&Ws[r][q] = *(const float4*)&W[(size_t)(c*32 + r)*F_ + q];
    }
}

__device__ __forceinline__ void mac_chunk_T(
    const float (*XsT)[PADT_], const float (*Ws)[128],
    int tx, int ty, ull acc2[8][4])
{
    #pragma unroll
    for (int k = 0; k < 32; ++k) {
        float a[8];
        *(float4*)&a[0] = *(const float4*)&XsT[k][ty*8];
        *(float4*)&a[4] = *(const float4*)&XsT[k][ty*8 + 4];
        ull b2[4];
        {
            ulonglong2 t0 = *(const ulonglong2*)&Ws[k][tx*8];
            ulonglong2 t1 = *(const ulonglong2*)&Ws[k][tx*8 + 4];
            b2[0] = t0.x; b2[1] = t0.y; b2[2] = t1.x; b2[3] = t1.y;
        }
        #pragma unroll
        for (int i = 0; i < 8; ++i) {
            ull a2 = dup2(a[i]);
            #pragma unroll
            for (int j = 0; j < 4; ++j) acc2[i][j] = ffma2(a2, b2[j], acc2[i][j]);
        }
    }
}

__device__ __forceinline__ void zero_acc(ull acc2[8][4]) {
    #pragma unroll
    for (int i = 0; i < 8; ++i)
        #pragma unroll
        for (int j = 0; j < 4; ++j) acc2[i][j] = 0ull;
}

// ---------------------------------------------------------------------------
// Fused: w1 = lrelu(x@W3+b3), w2 = lrelu(x@W4+b4), diag_i = w1_i . w2_i.
// ---------------------------------------------------------------------------
__global__ void __launch_bounds__(256) k_w1w2(
    const float* __restrict__ X,
    const float* __restrict__ W3, const float* __restrict__ b3,
    const float* __restrict__ W4, const float* __restrict__ b4,
    float* __restrict__ Y1, float* __restrict__ Y2, float* __restrict__ diag)
{
    __shared__ float XsT[32][PADT_];
    __shared__ float Ws[32][128];

    const int row0 = blockIdx.x * 128;
    const int tid  = threadIdx.x;
    const int tx   = tid & 15;
    const int ty   = tid >> 4;

    ull acc2[8][4];
    zero_acc(acc2);

    // ---- stage A: w1 ----
    for (int c = 0; c < 4; ++c) {
        load_XT_chunk(X, row0, c, tid, XsT);
        load_W_chunk(W3, c, tid, Ws);
        __syncthreads();
        mac_chunk_T(XsT, Ws, tx, ty, acc2);
        __syncthreads();
    }

    float w1v[8][8];
    {
        float bb[8];
        *(float4*)&bb[0] = *(const float4*)&b3[tx*8];
        *(float4*)&bb[4] = *(const float4*)&b3[tx*8 + 4];
        #pragma unroll
        for (int i = 0; i < 8; ++i) {
            const size_t r = (size_t)(row0 + ty*8 + i);
            #pragma unroll
            for (int j = 0; j < 4; ++j) {
                float2 f = unpk(acc2[i][j]);
                w1v[i][2*j]   = lrelu(f.x + bb[2*j]);
                w1v[i][2*j+1] = lrelu(f.y + bb[2*j+1]);
            }
            *(float4*)&Y1[r*F_ + tx*8]     = *(float4*)&w1v[i][0];
            *(float4*)&Y1[r*F_ + tx*8 + 4] = *(float4*)&w1v[i][4];
        }
    }

    // ---- stage B: w2 + diag ----
    zero_acc(acc2);
    for (int c = 0; c < 4; ++c) {
        load_XT_chunk(X, row0, c, tid, XsT);
        load_W_chunk(W4, c, tid, Ws);
        __syncthreads();
        mac_chunk_T(XsT, Ws, tx, ty, acc2);
        __syncthreads();
    }

    {
        float bb[8];
        *(float4*)&bb[0] = *(const float4*)&b4[tx*8];
        *(float4*)&bb[4] = *(const float4*)&b4[tx*8 + 4];
        #pragma unroll
        for (int i = 0; i < 8; ++i) {
            const size_t r = (size_t)(row0 + ty*8 + i);
            float v[8];
            #pragma unroll
            for (int j = 0; j < 4; ++j) {
                float2 f = unpk(acc2[i][j]);
                v[2*j]   = lrelu(f.x + bb[2*j]);
                v[2*j+1] = lrelu(f.y + bb[2*j+1]);
            }
            *(float4*)&Y2[r*F_ + tx*8]     = *(float4*)&v[0];
            *(float4*)&Y2[r*F_ + tx*8 + 4] = *(float4*)&v[4];
            float d = 0.f;
            #pragma unroll
            for (int j = 0; j < 8; ++j) d += w1v[i][j] * v[j];
            d += __shfl_xor_sync(0xffffffffu, d, 1);
            d += __shfl_xor_sync(0xffffffffu, d, 2);
            d += __shfl_xor_sync(0xffffffffu, d, 4);
            d += __shfl_xor_sync(0xffffffffu, d, 8);
            if (tx == 0) diag[r] = d;
        }
    }
}

// ---------------------------------------------------------------------------
// Split-K partials of S[b] = w2[b]^T @ x[b]. grid = (NSPLIT_, B_).
// ---------------------------------------------------------------------------
__global__ void __launch_bounds__(256) calc_S(
    const float* __restrict__ w2, const float* __restrict__ x,
    float* __restrict__ Spart)
{
    const int split = blockIdx.x;
    const int b     = blockIdx.y;
    const int k0    = b*N_ + split*128;

    __shared__ float As[32][128];
    __shared__ float Bs[32][128];

    const int tid = threadIdx.x;
    const int tx  = tid & 15;
    const int ty  = tid >> 4;

    ull acc2[8][4];
    zero_acc(acc2);

    for (int c = 0; c < 4; ++c) {
        #pragma unroll
        for (int i = 0; i < 4; ++i) {
            int f4 = tid + i*256;
            int r  = f4 >> 5;
            int q  = (f4 & 31) << 2;
            size_t g = (size_t)(k0 + c*32 + r)*F_ + q;
            *(float4*)&As[r][q] = *(const float4*)&w2[g];
            *(float4*)&Bs[r][q] = *(const float4*)&x[g];
        }
        __syncthreads();

        #pragma unroll
        for (int k = 0; k < 32; ++k) {
            float a[8];
            *(float4*)&a[0] = *(const float4*)&As[k][ty*8];
            *(float4*)&a[4] = *(const float4*)&As[k][ty*8 + 4];
            ull b2[4];
            {
                ulonglong2 t0 = *(const ulonglong2*)&Bs[k][tx*8];
                ulonglong2 t1 = *(const ulonglong2*)&Bs[k][tx*8 + 4];
                b2[0] = t0.x; b2[1] = t0.y; b2[2] = t1.x; b2[3] = t1.y;
            }
            #pragma unroll
            for (int i = 0; i < 8; ++i) {
                ull a2 = dup2(a[i]);
                #pragma unroll
                for (int j = 0; j < 4; ++j) acc2[i][j] = ffma2(a2, b2[j], acc2[i][j]);
            }
        }
        __syncthreads();
    }

    float* out = Spart + ((size_t)b*NSPLIT_ + split)*F_*F_;
    #pragma unroll
    for (int i = 0; i < 8; ++i) {
        float v[8];
        #pragma unroll
        for (int j = 0; j < 4; ++j) {
            float2 f = unpk(acc2[i][j]);
            v[2*j] = f.x; v[2*j+1] = f.y;
        }
        *(float4*)&out[(size_t)(ty*8 + i)*F_ + tx*8]     = *(float4*)&v[0];
        *(float4*)&out[(size_t)(ty*8 + i)*F_ + tx*8 + 4] = *(float4*)&v[4];
    }
}

// Deterministic float4 reduction of split-K partials
__global__ void __launch_bounds__(256) reduce_S(
    const float4* __restrict__ Sp, float4* __restrict__ S)
{
    int idx = blockIdx.x*256 + threadIdx.x;
    int b   = idx >> 12;
    int ij  = idx & 4095;
    const float4* p = Sp + (size_t)b*NSPLIT_*4096 + ij;
    float4 s = p[0];
    #pragma unroll
    for (int t = 1; t < NSPLIT_; ++t) {
        float4 v = p[(size_t)t*4096];
        s.x += v.x; s.y += v.y; s.z += v.z; s.w += v.w;
    }
    S[idx] = s;
}

// ---------------------------------------------------------------------------
// Fused: msg = (w1@S[b] - diag.*x)/(N-1), then out = lrelu(msg@W5+b5) + x.
// msg lives in registers between stages; staged chunkwise into XsT for GEMM2.
// ---------------------------------------------------------------------------
__global__ void __launch_bounds__(256) k_msg_out(
    const float* __restrict__ w1, const float* __restrict__ diag,
    const float* __restrict__ x,  const float* __restrict__ S,
    const float* __restrict__ W5, const float* __restrict__ b5,
    float* __restrict__ out)
{
    const int row0 = blockIdx.x * 128;
    const int b    = row0 >> 11;
    const float* Sb = S + (size_t)b*F_*F_;

    __shared__ float XsT[32][PADT_];
    __shared__ float Ws[32][128];
    __shared__ float dsh[128];

    const int tid = threadIdx.x;
    const int tx  = tid & 15;
    const int ty  = tid >> 4;

    if (tid < 128) dsh[tid] = diag[row0 + tid];

    ull acc2[8][4];
    zero_acc(acc2);

    // ---- stage 1: acc = w1 @ Sb ----
    for (int c = 0; c < 4; ++c) {
        load_XT_chunk(w1, row0, c, tid, XsT);
        load_W_chunk(Sb, c, tid, Ws);
        __syncthreads();
        mac_chunk_T(XsT, Ws, tx, ty, acc2);
        __syncthreads();
    }

    // msg values in registers
    float msgv[8][8];
    #pragma unroll
    for (int i = 0; i < 8; ++i) {
        const int m = ty*8 + i;
        const size_t r = (size_t)(row0 + m);
        const float d = dsh[m];
        float xv[8];
        *(float4*)&xv[0] = *(const float4*)&x[r*F_ + tx*8];
        *(float4*)&xv[4] = *(const float4*)&x[r*F_ + tx*8 + 4];
        #pragma unroll
        for (int j = 0; j < 4; ++j) {
            float2 f = unpk(acc2[i][j]);
            msgv[i][2*j]   = (f.x - d*xv[2*j])   * INV_NM1_;
            msgv[i][2*j+1] = (f.y - d*xv[2*j+1]) * INV_NM1_;
        }
    }

    // ---- stage 2: out = lrelu(msg @ W5 + b5) + x ----
    zero_acc(acc2);
    for (int c = 0; c < 4; ++c) {
        // threads owning cols of this k-chunk write msg^T into XsT
        if ((tx >> 2) == c) {
            #pragma unroll
            for (int jj = 0; jj < 8; ++jj) {
                int kk = (tx & 3)*8 + jj;
                #pragma unroll
                for (int i = 0; i < 8; ++i)
                    XsT[kk][ty*8 + i] = msgv[i][jj];
            }
        }
        load_W_chunk(W5, c, tid, Ws);
        __syncthreads();
        mac_chunk_T(XsT, Ws, tx, ty, acc2);
        __syncthreads();
    }

    {
        float bb[8];
        *(float4*)&bb[0] = *(const float4*)&b5[tx*8];
        *(float4*)&bb[4] = *(const float4*)&b5[tx*8 + 4];
        #pragma unroll
        for (int i = 0; i < 8; ++i) {
            const size_t r = (size_t)(row0 + ty*8 + i);
            float xv[8], v[8];
            *(float4*)&xv[0] = *(const float4*)&x[r*F_ + tx*8];
            *(float4*)&xv[4] = *(const float4*)&x[r*F_ + tx*8 + 4];
            #pragma unroll
            for (int j = 0; j < 4; ++j) {
                float2 f = unpk(acc2[i][j]);
                v[2*j]   = lrelu(f.x + bb[2*j])   + xv[2*j];
                v[2*j+1] = lrelu(f.y + bb[2*j+1]) + xv[2*j+1];
            }
            *(float4*)&out[r*F_ + tx*8]     = *(float4*)&v[0];
            *(float4*)&out[r*F_ + tx*8 + 4] = *(float4*)&v[4];
        }
    }
}

// ---------------------------------------------------------------------------
extern "C" void kernel_launch(void* const* d_in, const int* in_sizes, int n_in,
                              void* d_out, int out_size)
{
    const float* x  = (const float*)d_in[0];
    const float* W3 = (const float*)d_in[1];
    const float* b3 = (const float*)d_in[2];
    const float* W4 = (const float*)d_in[3];
    const float* b4 = (const float*)d_in[4];
    const float* W5 = (const float*)d_in[5];
    const float* b5 = (const float*)d_in[6];
    float* out = (float*)d_out;

    float *pw1, *pw2, *pdg, *pSp, *pS;
    cudaGetSymbolAddress((void**)&pw1, g_w1);
    cudaGetSymbolAddress((void**)&pw2, g_w2);
    cudaGetSymbolAddress((void**)&pdg, g_diag);
    cudaGetSymbolAddress((void**)&pSp, g_Spart);
    cudaGetSymbolAddress((void**)&pS,  g_S);

    for (int l = 0; l < LAYERS_; ++l) {
        const float* xin = l ? out : x;
        const float* W3l = W3 + (size_t)l*F_*F_;
        const float* b3l = b3 + (size_t)l*F_;
        const float* W4l = W4 + (size_t)l*F_*F_;
        const float* b4l = b4 + (size_t)l*F_;
        const float* W5l = W5 + (size_t)l*F_*F_;
        const float* b5l = b5 + (size_t)l*F_;

        k_w1w2<<<M_/128, 256>>>(xin, W3l, b3l, W4l, b4l, pw1, pw2, pdg);
        calc_S<<<dim3(NSPLIT_, B_), 256>>>(pw2, xin, pSp);
        reduce_S<<<(B_*F_*F_)/(4*256), 256>>>((const float4*)pSp, (float4*)pS);
        k_msg_out<<<M_/128, 256>>>(pw1, pdg, xin, pS, W5l, b5l, out);
    }
}

// round 7
// speedup vs baseline: 1.0015x; 1.0015x over previous
#include <cuda_runtime.h>

// Problem constants
#define B_ 8
#define N_ 2048
#define F_ 128
#define M_ (B_*N_)          // 16384 total rows
#define LAYERS_ 2
#define NSPLIT_ 16
#define SLOPE_ 0.1f
#define INV_NM1_ (1.0f/2047.0f)
#define PADT_ 132           // XsT row pad: 132*4 bytes = multiple of 16 (float4-safe)

typedef unsigned long long ull;

// Scratch (device globals; no cudaMalloc allowed)
__device__ float g_w1[M_*F_];
__device__ float g_w2[M_*F_];
__device__ float g_diag[M_];
__device__ float g_Spart[B_*NSPLIT_*F_*F_];
__device__ float g_S[B_*F_*F_];

__device__ __forceinline__ float lrelu(float v) { return v >= 0.f ? v : SLOPE_*v; }

// ---- packed fp32x2 helpers (sm_100+: one FFMA2 issue = 2 FMAs) ----
__device__ __forceinline__ ull dup2(float a) {
    ull r; asm("mov.b64 %0, {%1, %1};" : "=l"(r) : "f"(a)); return r;
}
__device__ __forceinline__ ull ffma2(ull a, ull b, ull c) {
    ull d; asm("fma.rn.f32x2 %0, %1, %2, %3;" : "=l"(d) : "l"(a), "l"(b), "l"(c));
    return d;
}
__device__ __forceinline__ float2 unpk(ull v) {
    float2 f; asm("mov.b64 {%0, %1}, %2;" : "=f"(f.x), "=f"(f.y) : "l"(v)); return f;
}

// ---------------------------------------------------------------------------
// Shared tile helpers. A transposed: XsT[k][row] (pad PADT_). B: Ws[k][col].
// 256 threads: tx = tid&15 (8 cols), ty = tid>>4 (8 rows).
// ---------------------------------------------------------------------------
__device__ __forceinline__ void load_XT_chunk(
    const float* __restrict__ X, int row0, int c, int tid, float (*XsT)[PADT_])
{
    #pragma unroll
    for (int i = 0; i < 4; ++i) {
        int f4 = tid + i*256;
        int r  = f4 >> 3;             // 0..127
        int kq = (f4 & 7) << 2;       // 0..28
        float4 v = *(const float4*)&X[(size_t)(row0 + r)*F_ + c*32 + kq];
        XsT[kq+0][r] = v.x; XsT[kq+1][r] = v.y;
        XsT[kq+2][r] = v.z; XsT[kq+3][r] = v.w;
    }
}

__device__ __forceinline__ void load_W_chunk(
    const float* __restrict__ W, int c, int tid, float (*Ws)[128])
{
    #pragma unroll
    for (int i = 0; i < 4; ++i) {
        int f4 = tid + i*256;
        int r  = f4 >> 5;
        int q  = (f4 & 31) << 2;
        *(float4*)&Ws[r][q] = *(const float4*)&W[(size_t)(c*32 + r)*F_ + q];
    }
}

__device__ __forceinline__ void mac_chunk_T(
    const float (*XsT)[PADT_], const float (*Ws)[128],
    int tx, int ty, ull acc2[8][4])
{
    #pragma unroll
    for (int k = 0; k < 32; ++k) {
        float a[8];
        *(float4*)&a[0] = *(const float4*)&XsT[k][ty*8];
        *(float4*)&a[4] = *(const float4*)&XsT[k][ty*8 + 4];
        ull b2[4];
        {
            ulonglong2 t0 = *(const ulonglong2*)&Ws[k][tx*8];
            ulonglong2 t1 = *(const ulonglong2*)&Ws[k][tx*8 + 4];
            b2[0] = t0.x; b2[1] = t0.y; b2[2] = t1.x; b2[3] = t1.y;
        }
        #pragma unroll
        for (int i = 0; i < 8; ++i) {
            ull a2 = dup2(a[i]);
            #pragma unroll
            for (int j = 0; j < 4; ++j) acc2[i][j] = ffma2(a2, b2[j], acc2[i][j]);
        }
    }
}

__device__ __forceinline__ void zero_acc(ull acc2[8][4]) {
    #pragma unroll
    for (int i = 0; i < 8; ++i)
        #pragma unroll
        for (int j = 0; j < 4; ++j) acc2[i][j] = 0ull;
}

// ---------------------------------------------------------------------------
// Fused: w1 = lrelu(x@W3+b3), w2 = lrelu(x@W4+b4), diag_i = w1_i . w2_i.
// ---------------------------------------------------------------------------
__global__ void __launch_bounds__(256) k_w1w2(
    const float* __restrict__ X,
    const float* __restrict__ W3, const float* __restrict__ b3,
    const float* __restrict__ W4, const float* __restrict__ b4,
    float* __restrict__ Y1, float* __restrict__ Y2, float* __restrict__ diag)
{
    __shared__ float XsT[32][PADT_];
    __shared__ float Ws[32][128];

    const int row0 = blockIdx.x * 128;
    const int tid  = threadIdx.x;
    const int tx   = tid & 15;
    const int ty   = tid >> 4;

    ull acc2[8][4];
    zero_acc(acc2);

    // ---- stage A: w1 ----
    for (int c = 0; c < 4; ++c) {
        load_XT_chunk(X, row0, c, tid, XsT);
        load_W_chunk(W3, c, tid, Ws);
        __syncthreads();
        mac_chunk_T(XsT, Ws, tx, ty, acc2);
        __syncthreads();
    }

    float w1v[8][8];
    {
        float bb[8];
        *(float4*)&bb[0] = *(const float4*)&b3[tx*8];
        *(float4*)&bb[4] = *(const float4*)&b3[tx*8 + 4];
        #pragma unroll
        for (int i = 0; i < 8; ++i) {
            const size_t r = (size_t)(row0 + ty*8 + i);
            #pragma unroll
            for (int j = 0; j < 4; ++j) {
                float2 f = unpk(acc2[i][j]);
                w1v[i][2*j]   = lrelu(f.x + bb[2*j]);
                w1v[i][2*j+1] = lrelu(f.y + bb[2*j+1]);
            }
            *(float4*)&Y1[r*F_ + tx*8]     = *(float4*)&w1v[i][0];
            *(float4*)&Y1[r*F_ + tx*8 + 4] = *(float4*)&w1v[i][4];
        }
    }

    // ---- stage B: w2 + diag ----
    zero_acc(acc2);
    for (int c = 0; c < 4; ++c) {
        load_XT_chunk(X, row0, c, tid, XsT);
        load_W_chunk(W4, c, tid, Ws);
        __syncthreads();
        mac_chunk_T(XsT, Ws, tx, ty, acc2);
        __syncthreads();
    }

    {
        float bb[8];
        *(float4*)&bb[0] = *(const float4*)&b4[tx*8];
        *(float4*)&bb[4] = *(const float4*)&b4[tx*8 + 4];
        #pragma unroll
        for (int i = 0; i < 8; ++i) {
            const size_t r = (size_t)(row0 + ty*8 + i);
            float v[8];
            #pragma unroll
            for (int j = 0; j < 4; ++j) {
                float2 f = unpk(acc2[i][j]);
                v[2*j]   = lrelu(f.x + bb[2*j]);
                v[2*j+1] = lrelu(f.y + bb[2*j+1]);
            }
            *(float4*)&Y2[r*F_ + tx*8]     = *(float4*)&v[0];
            *(float4*)&Y2[r*F_ + tx*8 + 4] = *(float4*)&v[4];
            float d = 0.f;
            #pragma unroll
            for (int j = 0; j < 8; ++j) d += w1v[i][j] * v[j];
            d += __shfl_xor_sync(0xffffffffu, d, 1);
            d += __shfl_xor_sync(0xffffffffu, d, 2);
            d += __shfl_xor_sync(0xffffffffu, d, 4);
            d += __shfl_xor_sync(0xffffffffu, d, 8);
            if (tx == 0) diag[r] = d;
        }
    }
}

// ---------------------------------------------------------------------------
// Split-K partials of S[b] = w2[b]^T @ x[b]. grid = (NSPLIT_, B_).
// ---------------------------------------------------------------------------
__global__ void __launch_bounds__(256) calc_S(
    const float* __restrict__ w2, const float* __restrict__ x,
    float* __restrict__ Spart)
{
    const int split = blockIdx.x;
    const int b     = blockIdx.y;
    const int k0    = b*N_ + split*128;

    __shared__ float As[32][128];
    __shared__ float Bs[32][128];

    const int tid = threadIdx.x;
    const int tx  = tid & 15;
    const int ty  = tid >> 4;

    ull acc2[8][4];
    zero_acc(acc2);

    for (int c = 0; c < 4; ++c) {
        #pragma unroll
        for (int i = 0; i < 4; ++i) {
            int f4 = tid + i*256;
            int r  = f4 >> 5;
            int q  = (f4 & 31) << 2;
            size_t g = (size_t)(k0 + c*32 + r)*F_ + q;
            *(float4*)&As[r][q] = *(const float4*)&w2[g];
            *(float4*)&Bs[r][q] = *(const float4*)&x[g];
        }
        __syncthreads();

        #pragma unroll
        for (int k = 0; k < 32; ++k) {
            float a[8];
            *(float4*)&a[0] = *(const float4*)&As[k][ty*8];
            *(float4*)&a[4] = *(const float4*)&As[k][ty*8 + 4];
            ull b2[4];
            {
                ulonglong2 t0 = *(const ulonglong2*)&Bs[k][tx*8];
                ulonglong2 t1 = *(const ulonglong2*)&Bs[k][tx*8 + 4];
                b2[0] = t0.x; b2[1] = t0.y; b2[2] = t1.x; b2[3] = t1.y;
            }
            #pragma unroll
            for (int i = 0; i < 8; ++i) {
                ull a2 = dup2(a[i]);
                #pragma unroll
                for (int j = 0; j < 4; ++j) acc2[i][j] = ffma2(a2, b2[j], acc2[i][j]);
            }
        }
        __syncthreads();
    }

    float* out = Spart + ((size_t)b*NSPLIT_ + split)*F_*F_;
    #pragma unroll
    for (int i = 0; i < 8; ++i) {
        float v[8];
        #pragma unroll
        for (int j = 0; j < 4; ++j) {
            float2 f = unpk(acc2[i][j]);
            v[2*j] = f.x; v[2*j+1] = f.y;
        }
        *(float4*)&out[(size_t)(ty*8 + i)*F_ + tx*8]     = *(float4*)&v[0];
        *(float4*)&out[(size_t)(ty*8 + i)*F_ + tx*8 + 4] = *(float4*)&v[4];
    }
}

// Deterministic float4 reduction of split-K partials
__global__ void __launch_bounds__(256) reduce_S(
    const float4* __restrict__ Sp, float4* __restrict__ S)
{
    int idx = blockIdx.x*256 + threadIdx.x;
    int b   = idx >> 12;
    int ij  = idx & 4095;
    const float4* p = Sp + (size_t)b*NSPLIT_*4096 + ij;
    float4 s = p[0];
    #pragma unroll
    for (int t = 1; t < NSPLIT_; ++t) {
        float4 v = p[(size_t)t*4096];
        s.x += v.x; s.y += v.y; s.z += v.z; s.w += v.w;
    }
    S[idx] = s;
}

// ---------------------------------------------------------------------------
// Fused: msg = (w1@S[b] - diag.*x)/(N-1), then out = lrelu(msg@W5+b5) + x.
// msg lives in registers between stages; staged chunkwise into XsT for GEMM2.
// ---------------------------------------------------------------------------
__global__ void __launch_bounds__(256) k_msg_out(
    const float* __restrict__ w1, const float* __restrict__ diag,
    const float* __restrict__ x,  const float* __restrict__ S,
    const float* __restrict__ W5, const float* __restrict__ b5,
    float* __restrict__ out)
{
    const int row0 = blockIdx.x * 128;
    const int b    = row0 >> 11;
    const float* Sb = S + (size_t)b*F_*F_;

    __shared__ float XsT[32][PADT_];
    __shared__ float Ws[32][128];
    __shared__ float dsh[128];

    const int tid = threadIdx.x;
    const int tx  = tid & 15;
    const int ty  = tid >> 4;

    if (tid < 128) dsh[tid] = diag[row0 + tid];

    ull acc2[8][4];
    zero_acc(acc2);

    // ---- stage 1: acc = w1 @ Sb ----
    for (int c = 0; c < 4; ++c) {
        load_XT_chunk(w1, row0, c, tid, XsT);
        load_W_chunk(Sb, c, tid, Ws);
        __syncthreads();
        mac_chunk_T(XsT, Ws, tx, ty, acc2);
        __syncthreads();
    }

    // msg values in registers
    float msgv[8][8];
    #pragma unroll
    for (int i = 0; i < 8; ++i) {
        const int m = ty*8 + i;
        const size_t r = (size_t)(row0 + m);
        const float d = dsh[m];
        float xv[8];
        *(float4*)&xv[0] = *(const float4*)&x[r*F_ + tx*8];
        *(float4*)&xv[4] = *(const float4*)&x[r*F_ + tx*8 + 4];
        #pragma unroll
        for (int j = 0; j < 4; ++j) {
            float2 f = unpk(acc2[i][j]);
            msgv[i][2*j]   = (f.x - d*xv[2*j])   * INV_NM1_;
            msgv[i][2*j+1] = (f.y - d*xv[2*j+1]) * INV_NM1_;
        }
    }

    // ---- stage 2: out = lrelu(msg @ W5 + b5) + x ----
    zero_acc(acc2);
    for (int c = 0; c < 4; ++c) {
        // threads owning cols of this k-chunk write msg^T into XsT
        if ((tx >> 2) == c) {
            #pragma unroll
            for (int jj = 0; jj < 8; ++jj) {
                int kk = (tx & 3)*8 + jj;
                #pragma unroll
                for (int i = 0; i < 8; ++i)
                    XsT[kk][ty*8 + i] = msgv[i][jj];
            }
        }
        load_W_chunk(W5, c, tid, Ws);
        __syncthreads();
        mac_chunk_T(XsT, Ws, tx, ty, acc2);
        __syncthreads();
    }

    {
        float bb[8];
        *(float4*)&bb[0] = *(const float4*)&b5[tx*8];
        *(float4*)&bb[4] = *(const float4*)&b5[tx*8 + 4];
        #pragma unroll
        for (int i = 0; i < 8; ++i) {
            const size_t r = (size_t)(row0 + ty*8 + i);
            float xv[8], v[8];
            *(float4*)&xv[0] = *(const float4*)&x[r*F_ + tx*8];
            *(float4*)&xv[4] = *(const float4*)&x[r*F_ + tx*8 + 4];
            #pragma unroll
            for (int j = 0; j < 4; ++j) {
                float2 f = unpk(acc2[i][j]);
                v[2*j]   = lrelu(f.x + bb[2*j])   + xv[2*j];
                v[2*j+1] = lrelu(f.y + bb[2*j+1]) + xv[2*j+1];
            }
            *(float4*)&out[r*F_ + tx*8]     = *(float4*)&v[0];
            *(float4*)&out[r*F_ + tx*8 + 4] = *(float4*)&v[4];
        }
    }
}

// ---------------------------------------------------------------------------
extern "C" void kernel_launch(void* const* d_in, const int* in_sizes, int n_in,
                              void* d_out, int out_size)
{
    const float* x  = (const float*)d_in[0];
    const float* W3 = (const float*)d_in[1];
    const float* b3 = (const float*)d_in[2];
    const float* W4 = (const float*)d_in[3];
    const float* b4 = (const float*)d_in[4];
    const float* W5 = (const float*)d_in[5];
    const float* b5 = (const float*)d_in[6];
    float* out = (float*)d_out;

    float *pw1, *pw2, *pdg, *pSp, *pS;
    cudaGetSymbolAddress((void**)&pw1, g_w1);
    cudaGetSymbolAddress((void**)&pw2, g_w2);
    cudaGetSymbolAddress((void**)&pdg, g_diag);
    cudaGetSymbolAddress((void**)&pSp, g_Spart);
    cudaGetSymbolAddress((void**)&pS,  g_S);

    for (int l = 0; l < LAYERS_; ++l) {
        const float* xin = l ? out : x;
        const float* W3l = W3 + (size_t)l*F_*F_;
        const float* b3l = b3 + (size_t)l*F_;
        const float* W4l = W4 + (size_t)l*F_*F_;
        const float* b4l = b4 + (size_t)l*F_;
        const float* W5l = W5 + (size_t)l*F_*F_;
        const float* b5l = b5 + (size_t)l*F_;

        k_w1w2<<<M_/128, 256>>>(xin, W3l, b3l, W4l, b4l, pw1, pw2, pdg);
        calc_S<<<dim3(NSPLIT_, B_), 256>>>(pw2, xin, pSp);
        reduce_S<<<(B_*F_*F_)/(4*256), 256>>>((const float4*)pSp, (float4*)pS);
        k_msg_out<<<M_/128, 256>>>(pw1, pdg, xin, pS, W5l, b5l, out);
    }
}

// round 8
// speedup vs baseline: 1.1655x; 1.1638x over previous
#include <cuda_runtime.h>

// Problem constants
#define B_ 8
#define N_ 2048
#define F_ 128
#define M_ (B_*N_)          // 16384 total rows
#define LAYERS_ 2
#define NSPLIT_ 16
#define SLOPE_ 0.1f
#define INV_NM1_ (1.0f/2047.0f)
#define PADT_ 132           // XsT row pad: 132*4 = 528 bytes, multiple of 16 (float4-safe)
#define NT_ 512             // threads per block

typedef unsigned long long ull;

// Scratch (device globals; no cudaMalloc allowed)
__device__ float g_w1[M_*F_];
__device__ float g_w2[M_*F_];
__device__ float g_diag[M_];
__device__ float g_Spart[B_*NSPLIT_*F_*F_];
__device__ float g_S[B_*F_*F_];

__device__ __forceinline__ float lrelu(float v) { return v >= 0.f ? v : SLOPE_*v; }

// ---- packed fp32x2 helpers (sm_100+: one FFMA2 issue = 2 FMAs) ----
__device__ __forceinline__ ull dup2(float a) {
    ull r; asm("mov.b64 %0, {%1, %1};" : "=l"(r) : "f"(a)); return r;
}
__device__ __forceinline__ ull ffma2(ull a, ull b, ull c) {
    ull d; asm("fma.rn.f32x2 %0, %1, %2, %3;" : "=l"(d) : "l"(a), "l"(b), "l"(c));
    return d;
}
__device__ __forceinline__ float2 unpk(ull v) {
    float2 f; asm("mov.b64 {%0, %1}, %2;" : "=f"(f.x), "=f"(f.y) : "l"(v)); return f;
}

// ---------------------------------------------------------------------------
// 512 threads: tx = tid&31 (4-col groups -> 128 cols), ty = tid>>5 (8-row groups).
// A transposed in smem: XsT[k][row] (pad PADT_). B: Ws[k][col].
// Per-thread tile: 8 rows x 4 cols, acc2[8][2] packed pairs.
// ---------------------------------------------------------------------------
__device__ __forceinline__ void load_XT_chunk(
    const float* __restrict__ X, int row0, int c, int tid, float (*XsT)[PADT_])
{
    #pragma unroll
    for (int i = 0; i < 2; ++i) {
        int f4 = tid + i*NT_;
        int r  = f4 >> 3;             // 0..127
        int kq = (f4 & 7) << 2;       // 0..28
        float4 v = *(const float4*)&X[(size_t)(row0 + r)*F_ + c*32 + kq];
        XsT[kq+0][r] = v.x; XsT[kq+1][r] = v.y;
        XsT[kq+2][r] = v.z; XsT[kq+3][r] = v.w;
    }
}

__device__ __forceinline__ void load_W_chunk(
    const float* __restrict__ W, int c, int tid, float (*Ws)[128])
{
    #pragma unroll
    for (int i = 0; i < 2; ++i) {
        int f4 = tid + i*NT_;
        int r  = f4 >> 5;
        int q  = (f4 & 31) << 2;
        *(float4*)&Ws[r][q] = *(const float4*)&W[(size_t)(c*32 + r)*F_ + q];
    }
}

__device__ __forceinline__ void mac_chunk(
    const float (*XsT)[PADT_], const float (*Ws)[128],
    int tx, int ty, ull acc2[8][2])
{
    #pragma unroll
    for (int k = 0; k < 32; ++k) {
        float a[8];
        *(float4*)&a[0] = *(const float4*)&XsT[k][ty*8];       // broadcast
        *(float4*)&a[4] = *(const float4*)&XsT[k][ty*8 + 4];   // broadcast
        ulonglong2 b2 = *(const ulonglong2*)&Ws[k][tx*4];
        #pragma unroll
        for (int i = 0; i < 8; ++i) {
            ull a2 = dup2(a[i]);
            acc2[i][0] = ffma2(a2, b2.x, acc2[i][0]);
            acc2[i][1] = ffma2(a2, b2.y, acc2[i][1]);
        }
    }
}

__device__ __forceinline__ void zero_acc(ull acc2[8][2]) {
    #pragma unroll
    for (int i = 0; i < 8; ++i) { acc2[i][0] = 0ull; acc2[i][1] = 0ull; }
}

// ---------------------------------------------------------------------------
// Fused: w1 = lrelu(x@W3+b3), w2 = lrelu(x@W4+b4), diag_i = w1_i . w2_i.
// ---------------------------------------------------------------------------
__global__ void __launch_bounds__(NT_) k_w1w2(
    const float* __restrict__ X,
    const float* __restrict__ W3, const float* __restrict__ b3,
    const float* __restrict__ W4, const float* __restrict__ b4,
    float* __restrict__ Y1, float* __restrict__ Y2, float* __restrict__ diag)
{
    __shared__ float XsT[32][PADT_];
    __shared__ float Ws[32][128];

    const int row0 = blockIdx.x * 128;
    const int tid  = threadIdx.x;
    const int tx   = tid & 31;
    const int ty   = tid >> 5;
    const int lane = tid & 31;

    ull acc2[8][2];
    zero_acc(acc2);

    // ---- stage A: w1 ----
    for (int c = 0; c < 4; ++c) {
        load_XT_chunk(X, row0, c, tid, XsT);
        load_W_chunk(W3, c, tid, Ws);
        __syncthreads();
        mac_chunk(XsT, Ws, tx, ty, acc2);
        __syncthreads();
    }

    float w1v[8][4];
    {
        float4 bb = *(const float4*)&b3[tx*4];
        #pragma unroll
        for (int i = 0; i < 8; ++i) {
            const size_t r = (size_t)(row0 + ty*8 + i);
            float2 f0 = unpk(acc2[i][0]);
            float2 f1 = unpk(acc2[i][1]);
            w1v[i][0] = lrelu(f0.x + bb.x);
            w1v[i][1] = lrelu(f0.y + bb.y);
            w1v[i][2] = lrelu(f1.x + bb.z);
            w1v[i][3] = lrelu(f1.y + bb.w);
            *(float4*)&Y1[r*F_ + tx*4] = *(float4*)&w1v[i][0];
        }
    }

    // ---- stage B: w2 + diag ----
    zero_acc(acc2);
    for (int c = 0; c < 4; ++c) {
        load_XT_chunk(X, row0, c, tid, XsT);
        load_W_chunk(W4, c, tid, Ws);
        __syncthreads();
        mac_chunk(XsT, Ws, tx, ty, acc2);
        __syncthreads();
    }

    {
        float4 bb = *(const float4*)&b4[tx*4];
        #pragma unroll
        for (int i = 0; i < 8; ++i) {
            const size_t r = (size_t)(row0 + ty*8 + i);
            float v[4];
            float2 f0 = unpk(acc2[i][0]);
            float2 f1 = unpk(acc2[i][1]);
            v[0] = lrelu(f0.x + bb.x);
            v[1] = lrelu(f0.y + bb.y);
            v[2] = lrelu(f1.x + bb.z);
            v[3] = lrelu(f1.y + bb.w);
            *(float4*)&Y2[r*F_ + tx*4] = *(float4*)&v[0];
            // diag partial: this warp's lanes cover all 128 cols of the same 8 rows
            float d = w1v[i][0]*v[0] + w1v[i][1]*v[1] + w1v[i][2]*v[2] + w1v[i][3]*v[3];
            d += __shfl_xor_sync(0xffffffffu, d, 1);
            d += __shfl_xor_sync(0xffffffffu, d, 2);
            d += __shfl_xor_sync(0xffffffffu, d, 4);
            d += __shfl_xor_sync(0xffffffffu, d, 8);
            d += __shfl_xor_sync(0xffffffffu, d, 16);
            if (lane == 0) diag[r] = d;
        }
    }
}

// ---------------------------------------------------------------------------
// Split-K partials of S[b] = w2[b]^T @ x[b]. grid = (NSPLIT_, B_).
// ---------------------------------------------------------------------------
__global__ void __launch_bounds__(NT_) calc_S(
    const float* __restrict__ w2, const float* __restrict__ x,
    float* __restrict__ Spart)
{
    const int split = blockIdx.x;
    const int b     = blockIdx.y;
    const int k0    = b*N_ + split*128;

    __shared__ float As[32][128];
    __shared__ float Bs[32][128];

    const int tid = threadIdx.x;
    const int tx  = tid & 31;
    const int ty  = tid >> 5;

    ull acc2[8][2];
    zero_acc(acc2);

    for (int c = 0; c < 4; ++c) {
        #pragma unroll
        for (int i = 0; i < 2; ++i) {
            int f4 = tid + i*NT_;
            int r  = f4 >> 5;
            int q  = (f4 & 31) << 2;
            size_t g = (size_t)(k0 + c*32 + r)*F_ + q;
            *(float4*)&As[r][q] = *(const float4*)&w2[g];
            *(float4*)&Bs[r][q] = *(const float4*)&x[g];
        }
        __syncthreads();

        #pragma unroll
        for (int k = 0; k < 32; ++k) {
            float a[8];
            *(float4*)&a[0] = *(const float4*)&As[k][ty*8];
            *(float4*)&a[4] = *(const float4*)&As[k][ty*8 + 4];
            ulonglong2 b2 = *(const ulonglong2*)&Bs[k][tx*4];
            #pragma unroll
            for (int i = 0; i < 8; ++i) {
                ull a2 = dup2(a[i]);
                acc2[i][0] = ffma2(a2, b2.x, acc2[i][0]);
                acc2[i][1] = ffma2(a2, b2.y, acc2[i][1]);
            }
        }
        __syncthreads();
    }

    float* out = Spart + ((size_t)b*NSPLIT_ + split)*F_*F_;
    #pragma unroll
    for (int i = 0; i < 8; ++i) {
        float v[4];
        float2 f0 = unpk(acc2[i][0]);
        float2 f1 = unpk(acc2[i][1]);
        v[0] = f0.x; v[1] = f0.y; v[2] = f1.x; v[3] = f1.y;
        *(float4*)&out[(size_t)(ty*8 + i)*F_ + tx*4] = *(float4*)&v[0];
    }
}

// Deterministic float4 reduction of split-K partials
__global__ void __launch_bounds__(256) reduce_S(
    const float4* __restrict__ Sp, float4* __restrict__ S)
{
    int idx = blockIdx.x*256 + threadIdx.x;
    int b   = idx >> 12;
    int ij  = idx & 4095;
    const float4* p = Sp + (size_t)b*NSPLIT_*4096 + ij;
    float4 s = p[0];
    #pragma unroll
    for (int t = 1; t < NSPLIT_; ++t) {
        float4 v = p[(size_t)t*4096];
        s.x += v.x; s.y += v.y; s.z += v.z; s.w += v.w;
    }
    S[idx] = s;
}

// ---------------------------------------------------------------------------
// Fused: msg = (w1@S[b] - diag.*x)/(N-1), then out = lrelu(msg@W5+b5) + x.
// msg in registers between stages; staged chunkwise into XsT for GEMM2.
// ---------------------------------------------------------------------------
__global__ void __launch_bounds__(NT_) k_msg_out(
    const float* __restrict__ w1, const float* __restrict__ diag,
    const float* __restrict__ x,  const float* __restrict__ S,
    const float* __restrict__ W5, const float* __restrict__ b5,
    float* __restrict__ out)
{
    const int row0 = blockIdx.x * 128;
    const int b    = row0 >> 11;
    const float* Sb = S + (size_t)b*F_*F_;

    __shared__ float XsT[32][PADT_];
    __shared__ float Ws[32][128];
    __shared__ float dsh[128];

    const int tid = threadIdx.x;
    const int tx  = tid & 31;
    const int ty  = tid >> 5;

    if (tid < 128) dsh[tid] = diag[row0 + tid];

    ull acc2[8][2];
    zero_acc(acc2);

    // ---- stage 1: acc = w1 @ Sb ----
    for (int c = 0; c < 4; ++c) {
        load_XT_chunk(w1, row0, c, tid, XsT);
        load_W_chunk(Sb, c, tid, Ws);
        __syncthreads();
        mac_chunk(XsT, Ws, tx, ty, acc2);
        __syncthreads();
    }

    // msg values in registers (8 rows x 4 cols)
    float msgv[8][4];
    #pragma unroll
    for (int i = 0; i < 8; ++i) {
        const int m = ty*8 + i;
        const size_t r = (size_t)(row0 + m);
        const float d = dsh[m];
        float4 xv = *(const float4*)&x[r*F_ + tx*4];
        float2 f0 = unpk(acc2[i][0]);
        float2 f1 = unpk(acc2[i][1]);
        msgv[i][0] = (f0.x - d*xv.x) * INV_NM1_;
        msgv[i][1] = (f0.y - d*xv.y) * INV_NM1_;
        msgv[i][2] = (f1.x - d*xv.z) * INV_NM1_;
        msgv[i][3] = (f1.y - d*xv.w) * INV_NM1_;
    }

    // ---- stage 2: out = lrelu(msg @ W5 + b5) + x ----
    zero_acc(acc2);
    for (int c = 0; c < 4; ++c) {
        // threads owning cols [c*32, c*32+32) write msg^T into XsT
        if ((tx >> 3) == c) {
            #pragma unroll
            for (int j = 0; j < 4; ++j) {
                int kk = (tx & 7)*4 + j;
                #pragma unroll
                for (int i = 0; i < 8; ++i)
                    XsT[kk][ty*8 + i] = msgv[i][j];
            }
        }
        load_W_chunk(W5, c, tid, Ws);
        __syncthreads();
        mac_chunk(XsT, Ws, tx, ty, acc2);
        __syncthreads();
    }

    {
        float4 bb = *(const float4*)&b5[tx*4];
        #pragma unroll
        for (int i = 0; i < 8; ++i) {
            const size_t r = (size_t)(row0 + ty*8 + i);
            float4 xv = *(const float4*)&x[r*F_ + tx*4];
            float v[4];
            float2 f0 = unpk(acc2[i][0]);
            float2 f1 = unpk(acc2[i][1]);
            v[0] = lrelu(f0.x + bb.x) + xv.x;
            v[1] = lrelu(f0.y + bb.y) + xv.y;
            v[2] = lrelu(f1.x + bb.z) + xv.z;
            v[3] = lrelu(f1.y + bb.w) + xv.w;
            *(float4*)&out[r*F_ + tx*4] = *(float4*)&v[0];
        }
    }
}

// ---------------------------------------------------------------------------
extern "C" void kernel_launch(void* const* d_in, const int* in_sizes, int n_in,
                              void* d_out, int out_size)
{
    const float* x  = (const float*)d_in[0];
    const float* W3 = (const float*)d_in[1];
    const float* b3 = (const float*)d_in[2];
    const float* W4 = (const float*)d_in[3];
    const float* b4 = (const float*)d_in[4];
    const float* W5 = (const float*)d_in[5];
    const float* b5 = (const float*)d_in[6];
    float* out = (float*)d_out;

    float *pw1, *pw2, *pdg, *pSp, *pS;
    cudaGetSymbolAddress((void**)&pw1, g_w1);
    cudaGetSymbolAddress((void**)&pw2, g_w2);
    cudaGetSymbolAddress((void**)&pdg, g_diag);
    cudaGetSymbolAddress((void**)&pSp, g_Spart);
    cudaGetSymbolAddress((void**)&pS,  g_S);

    for (int l = 0; l < LAYERS_; ++l) {
        const float* xin = l ? out : x;
        const float* W3l = W3 + (size_t)l*F_*F_;
        const float* b3l = b3 + (size_t)l*F_;
        const float* W4l = W4 + (size_t)l*F_*F_;
        const float* b4l = b4 + (size_t)l*F_;
        const float* W5l = W5 + (size_t)l*F_*F_;
        const float* b5l = b5 + (size_t)l*F_;

        k_w1w2<<<M_/128, NT_>>>(xin, W3l, b3l, W4l, b4l, pw1, pw2, pdg);
        calc_S<<<dim3(NSPLIT_, B_), NT_>>>(pw2, xin, pSp);
        reduce_S<<<(B_*F_*F_)/(4*256), 256>>>((const float4*)pSp, (float4*)pS);
        k_msg_out<<<M_/128, NT_>>>(pw1, pdg, xin, pS, W5l, b5l, out);
    }
}

// round 9
// speedup vs baseline: 1.2345x; 1.0592x over previous
#include <cuda_runtime.h>

// Problem constants
#define B_ 8
#define N_ 2048
#define F_ 128
#define M_ (B_*N_)          // 16384 total rows
#define LAYERS_ 2
#define NSPLIT_ 16
#define SLOPE_ 0.1f
#define INV_NM1_ (1.0f/2047.0f)
#define PADT_ 132           // XsT row pad: 132*4 = 528 bytes, multiple of 16
#define NT_ 512             // threads per block

typedef unsigned long long ull;

// Scratch (device globals; no cudaMalloc allowed)
__device__ float g_w1[M_*F_];
__device__ float g_w2[M_*F_];
__device__ float g_diag[M_];
__device__ float g_Spart[B_*NSPLIT_*F_*F_];
__device__ float g_S[B_*F_*F_];

__device__ __forceinline__ float lrelu(float v) { return v >= 0.f ? v : SLOPE_*v; }

// ---- packed fp32x2 helpers (sm_100+: one FFMA2 issue = 2 FMAs) ----
__device__ __forceinline__ ull dup2(float a) {
    ull r; asm("mov.b64 %0, {%1, %1};" : "=l"(r) : "f"(a)); return r;
}
__device__ __forceinline__ ull ffma2(ull a, ull b, ull c) {
    ull d; asm("fma.rn.f32x2 %0, %1, %2, %3;" : "=l"(d) : "l"(a), "l"(b), "l"(c));
    return d;
}
__device__ __forceinline__ float2 unpk(ull v) {
    float2 f; asm("mov.b64 {%0, %1}, %2;" : "=f"(f.x), "=f"(f.y) : "l"(v)); return f;
}

// ---------------------------------------------------------------------------
// 512 threads: tx = tid&31 (4 cols each -> 128 cols), ty = tid>>5 (8 rows each).
// A transposed in smem: XsT[k][row]. Row-pair packing: acc2[p][j] holds rows
// {ty*8+2p, ty*8+2p+1} of col tx*4+j; A-pairs load directly as LDS.128 (no dup).
// ---------------------------------------------------------------------------
__device__ __forceinline__ void load_XT_chunk(
    const float* __restrict__ X, int row0, int c, int tid, float (*XsT)[PADT_])
{
    #pragma unroll
    for (int i = 0; i < 2; ++i) {
        int f4 = tid + i*NT_;
        int r  = f4 >> 3;             // 0..127
        int kq = (f4 & 7) << 2;       // 0..28
        float4 v = *(const float4*)&X[(size_t)(row0 + r)*F_ + c*32 + kq];
        XsT[kq+0][r] = v.x; XsT[kq+1][r] = v.y;
        XsT[kq+2][r] = v.z; XsT[kq+3][r] = v.w;
    }
}

__device__ __forceinline__ void load_W_chunk(
    const float* __restrict__ W, int c, int tid, float (*Ws)[128])
{
    #pragma unroll
    for (int i = 0; i < 2; ++i) {
        int f4 = tid + i*NT_;
        int r  = f4 >> 5;
        int q  = (f4 & 31) << 2;
        *(float4*)&Ws[r][q] = *(const float4*)&W[(size_t)(c*32 + r)*F_ + q];
    }
}

__device__ __forceinline__ void load_a2(
    const float (*XsT)[PADT_], int k, int ty, ull a2[4])
{
    ulonglong2 t0 = *(const ulonglong2*)&XsT[k][ty*8];
    ulonglong2 t1 = *(const ulonglong2*)&XsT[k][ty*8 + 4];
    a2[0] = t0.x; a2[1] = t0.y; a2[2] = t1.x; a2[3] = t1.y;
}

__device__ __forceinline__ void mac_chunk(
    const float (*XsT)[PADT_], const float (*Ws)[128],
    int tx, int ty, ull acc2[4][4])
{
    #pragma unroll
    for (int k = 0; k < 32; ++k) {
        ull a2[4];
        load_a2(XsT, k, ty, a2);
        float4 bv = *(const float4*)&Ws[k][tx*4];
        ull b2[4] = { dup2(bv.x), dup2(bv.y), dup2(bv.z), dup2(bv.w) };
        #pragma unroll
        for (int p = 0; p < 4; ++p)
            #pragma unroll
            for (int j = 0; j < 4; ++j)
                acc2[p][j] = ffma2(a2[p], b2[j], acc2[p][j]);
    }
}

__device__ __forceinline__ void zero_acc(ull acc2[4][4]) {
    #pragma unroll
    for (int p = 0; p < 4; ++p)
        #pragma unroll
        for (int j = 0; j < 4; ++j) acc2[p][j] = 0ull;
}

// ---------------------------------------------------------------------------
// Fused single-pass: w1 = lrelu(x@W3+b3), w2 = lrelu(x@W4+b4), diag = w1.w2.
// One X-tile load feeds both accumulator sets.
// ---------------------------------------------------------------------------
__global__ void __launch_bounds__(NT_) k_w1w2(
    const float* __restrict__ X,
    const float* __restrict__ W3, const float* __restrict__ b3,
    const float* __restrict__ W4, const float* __restrict__ b4,
    float* __restrict__ Y1, float* __restrict__ Y2, float* __restrict__ diag)
{
    __shared__ float XsT[32][PADT_];
    __shared__ float Ws3[32][128];
    __shared__ float Ws4[32][128];

    const int row0 = blockIdx.x * 128;
    const int tid  = threadIdx.x;
    const int tx   = tid & 31;
    const int ty   = tid >> 5;
    const int lane = tid & 31;

    ull acc3[4][4], acc4[4][4];
    zero_acc(acc3); zero_acc(acc4);

    for (int c = 0; c < 4; ++c) {
        load_XT_chunk(X, row0, c, tid, XsT);
        load_W_chunk(W3, c, tid, Ws3);
        load_W_chunk(W4, c, tid, Ws4);
        __syncthreads();
        #pragma unroll
        for (int k = 0; k < 32; ++k) {
            ull a2[4];
            load_a2(XsT, k, ty, a2);
            float4 bv3 = *(const float4*)&Ws3[k][tx*4];
            float4 bv4 = *(const float4*)&Ws4[k][tx*4];
            ull b3d[4] = { dup2(bv3.x), dup2(bv3.y), dup2(bv3.z), dup2(bv3.w) };
            ull b4d[4] = { dup2(bv4.x), dup2(bv4.y), dup2(bv4.z), dup2(bv4.w) };
            #pragma unroll
            for (int p = 0; p < 4; ++p) {
                #pragma unroll
                for (int j = 0; j < 4; ++j) {
                    acc3[p][j] = ffma2(a2[p], b3d[j], acc3[p][j]);
                    acc4[p][j] = ffma2(a2[p], b4d[j], acc4[p][j]);
                }
            }
        }
        __syncthreads();
    }

    // Epilogue: unpack row-pairs, activate, store, diag reduce
    float4 bb3 = *(const float4*)&b3[tx*4];
    float4 bb4 = *(const float4*)&b4[tx*4];
    #pragma unroll
    for (int p = 0; p < 4; ++p) {
        float w1a[2][4], w2a[2][4];
        #pragma unroll
        for (int j = 0; j < 4; ++j) {
            float2 f3 = unpk(acc3[p][j]);
            float2 f4v = unpk(acc4[p][j]);
            const float* pb3 = (const float*)&bb3;
            const float* pb4 = (const float*)&bb4;
            w1a[0][j] = lrelu(f3.x + pb3[j]);
            w1a[1][j] = lrelu(f3.y + pb3[j]);
            w2a[0][j] = lrelu(f4v.x + pb4[j]);
            w2a[1][j] = lrelu(f4v.y + pb4[j]);
        }
        #pragma unroll
        for (int h = 0; h < 2; ++h) {
            const size_t r = (size_t)(row0 + ty*8 + 2*p + h);
            *(float4*)&Y1[r*F_ + tx*4] = *(float4*)&w1a[h][0];
            *(float4*)&Y2[r*F_ + tx*4] = *(float4*)&w2a[h][0];
            float d = w1a[h][0]*w2a[h][0] + w1a[h][1]*w2a[h][1]
                    + w1a[h][2]*w2a[h][2] + w1a[h][3]*w2a[h][3];
            d += __shfl_xor_sync(0xffffffffu, d, 1);
            d += __shfl_xor_sync(0xffffffffu, d, 2);
            d += __shfl_xor_sync(0xffffffffu, d, 4);
            d += __shfl_xor_sync(0xffffffffu, d, 8);
            d += __shfl_xor_sync(0xffffffffu, d, 16);
            if (lane == 0) diag[r] = d;
        }
    }
}

// ---------------------------------------------------------------------------
// Split-K partials of S[b] = w2[b]^T @ x[b]. grid = (NSPLIT_, B_).
// ---------------------------------------------------------------------------
__global__ void __launch_bounds__(NT_) calc_S(
    const float* __restrict__ w2, const float* __restrict__ x,
    float* __restrict__ Spart)
{
    const int split = blockIdx.x;
    const int b     = blockIdx.y;
    const int k0    = b*N_ + split*128;

    __shared__ float As[32][128];
    __shared__ float Bs[32][128];

    const int tid = threadIdx.x;
    const int tx  = tid & 31;
    const int ty  = tid >> 5;

    ull acc2[4][4];
    zero_acc(acc2);

    for (int c = 0; c < 4; ++c) {
        #pragma unroll
        for (int i = 0; i < 2; ++i) {
            int f4 = tid + i*NT_;
            int r  = f4 >> 5;
            int q  = (f4 & 31) << 2;
            size_t g = (size_t)(k0 + c*32 + r)*F_ + q;
            *(float4*)&As[r][q] = *(const float4*)&w2[g];
            *(float4*)&Bs[r][q] = *(const float4*)&x[g];
        }
        __syncthreads();

        #pragma unroll
        for (int k = 0; k < 32; ++k) {
            ull a2[4];
            {
                ulonglong2 t0 = *(const ulonglong2*)&As[k][ty*8];
                ulonglong2 t1 = *(const ulonglong2*)&As[k][ty*8 + 4];
                a2[0] = t0.x; a2[1] = t0.y; a2[2] = t1.x; a2[3] = t1.y;
            }
            float4 bv = *(const float4*)&Bs[k][tx*4];
            ull b2[4] = { dup2(bv.x), dup2(bv.y), dup2(bv.z), dup2(bv.w) };
            #pragma unroll
            for (int p = 0; p < 4; ++p)
                #pragma unroll
                for (int j = 0; j < 4; ++j)
                    acc2[p][j] = ffma2(a2[p], b2[j], acc2[p][j]);
        }
        __syncthreads();
    }

    float* out = Spart + ((size_t)b*NSPLIT_ + split)*F_*F_;
    #pragma unroll
    for (int p = 0; p < 4; ++p) {
        float v0[4], v1[4];
        #pragma unroll
        for (int j = 0; j < 4; ++j) {
            float2 f = unpk(acc2[p][j]);
            v0[j] = f.x; v1[j] = f.y;
        }
        *(float4*)&out[(size_t)(ty*8 + 2*p    )*F_ + tx*4] = *(float4*)&v0[0];
        *(float4*)&out[(size_t)(ty*8 + 2*p + 1)*F_ + tx*4] = *(float4*)&v1[0];
    }
}

// Deterministic float4 reduction of split-K partials
__global__ void __launch_bounds__(256) reduce_S(
    const float4* __restrict__ Sp, float4* __restrict__ S)
{
    int idx = blockIdx.x*256 + threadIdx.x;
    int b   = idx >> 12;
    int ij  = idx & 4095;
    const float4* p = Sp + (size_t)b*NSPLIT_*4096 + ij;
    float4 s = p[0];
    #pragma unroll
    for (int t = 1; t < NSPLIT_; ++t) {
        float4 v = p[(size_t)t*4096];
        s.x += v.x; s.y += v.y; s.z += v.z; s.w += v.w;
    }
    S[idx] = s;
}

// ---------------------------------------------------------------------------
// Fused: msg = (w1@S[b] - diag.*x)/(N-1), then out = lrelu(msg@W5+b5) + x.
// ---------------------------------------------------------------------------
__global__ void __launch_bounds__(NT_) k_msg_out(
    const float* __restrict__ w1, const float* __restrict__ diag,
    const float* __restrict__ x,  const float* __restrict__ S,
    const float* __restrict__ W5, const float* __restrict__ b5,
    float* __restrict__ out)
{
    const int row0 = blockIdx.x * 128;
    const int b    = row0 >> 11;
    const float* Sb = S + (size_t)b*F_*F_;

    __shared__ float XsT[32][PADT_];
    __shared__ float Ws[32][128];
    __shared__ float dsh[128];

    const int tid = threadIdx.x;
    const int tx  = tid & 31;
    const int ty  = tid >> 5;

    if (tid < 128) dsh[tid] = diag[row0 + tid];

    ull acc2[4][4];
    zero_acc(acc2);

    // ---- stage 1: acc = w1 @ Sb ----
    for (int c = 0; c < 4; ++c) {
        load_XT_chunk(w1, row0, c, tid, XsT);
        load_W_chunk(Sb, c, tid, Ws);
        __syncthreads();
        mac_chunk(XsT, Ws, tx, ty, acc2);
        __syncthreads();
    }

    // msg values in registers (8 rows x 4 cols)
    float msgv[8][4];
    #pragma unroll
    for (int p = 0; p < 4; ++p) {
        #pragma unroll
        for (int h = 0; h < 2; ++h) {
            const int i = 2*p + h;
            const int m = ty*8 + i;
            const size_t r = (size_t)(row0 + m);
            const float d = dsh[m];
            float4 xv = *(const float4*)&x[r*F_ + tx*4];
            const float* px = (const float*)&xv;
            #pragma unroll
            for (int j = 0; j < 4; ++j) {
                float2 f = unpk(acc2[p][j]);
                float a = h ? f.y : f.x;
                msgv[i][j] = (a - d*px[j]) * INV_NM1_;
            }
        }
    }

    // ---- stage 2: out = lrelu(msg @ W5 + b5) + x ----
    zero_acc(acc2);
    for (int c = 0; c < 4; ++c) {
        // threads owning cols [c*32, c*32+32) write msg^T into XsT
        if ((tx >> 3) == c) {
            #pragma unroll
            for (int j = 0; j < 4; ++j) {
                int kk = (tx & 7)*4 + j;
                #pragma unroll
                for (int i = 0; i < 8; ++i)
                    XsT[kk][ty*8 + i] = msgv[i][j];
            }
        }
        load_W_chunk(W5, c, tid, Ws);
        __syncthreads();
        mac_chunk(XsT, Ws, tx, ty, acc2);
        __syncthreads();
    }

    {
        float4 bb = *(const float4*)&b5[tx*4];
        const float* pb = (const float*)&bb;
        #pragma unroll
        for (int p = 0; p < 4; ++p) {
            #pragma unroll
            for (int h = 0; h < 2; ++h) {
                const size_t r = (size_t)(row0 + ty*8 + 2*p + h);
                float4 xv = *(const float4*)&x[r*F_ + tx*4];
                const float* px = (const float*)&xv;
                float v[4];
                #pragma unroll
                for (int j = 0; j < 4; ++j) {
                    float2 f = unpk(acc2[p][j]);
                    float a = h ? f.y : f.x;
                    v[j] = lrelu(a + pb[j]) + px[j];
                }
                *(float4*)&out[r*F_ + tx*4] = *(float4*)&v[0];
            }
        }
    }
}

// ---------------------------------------------------------------------------
extern "C" void kernel_launch(void* const* d_in, const int* in_sizes, int n_in,
                              void* d_out, int out_size)
{
    const float* x  = (const float*)d_in[0];
    const float* W3 = (const float*)d_in[1];
    const float* b3 = (const float*)d_in[2];
    const float* W4 = (const float*)d_in[3];
    const float* b4 = (const float*)d_in[4];
    const float* W5 = (const float*)d_in[5];
    const float* b5 = (const float*)d_in[6];
    float* out = (float*)d_out;

    float *pw1, *pw2, *pdg, *pSp, *pS;
    cudaGetSymbolAddress((void**)&pw1, g_w1);
    cudaGetSymbolAddress((void**)&pw2, g_w2);
    cudaGetSymbolAddress((void**)&pdg, g_diag);
    cudaGetSymbolAddress((void**)&pSp, g_Spart);
    cudaGetSymbolAddress((void**)&pS,  g_S);

    for (int l = 0; l < LAYERS_; ++l) {
        const float* xin = l ? out : x;
        const float* W3l = W3 + (size_t)l*F_*F_;
        const float* b3l = b3 + (size_t)l*F_;
        const float* W4l = W4 + (size_t)l*F_*F_;
        const float* b4l = b4 + (size_t)l*F_;
        const float* W5l = W5 + (size_t)l*F_*F_;
        const float* b5l = b5 + (size_t)l*F_;

        k_w1w2<<<M_/128, NT_>>>(xin, W3l, b3l, W4l, b4l, pw1, pw2, pdg);
        calc_S<<<dim3(NSPLIT_, B_), NT_>>>(pw2, xin, pSp);
        reduce_S<<<(B_*F_*F_)/(4*256), 256>>>((const float4*)pSp, (float4*)pS);
        k_msg_out<<<M_/128, NT_>>>(pw1, pdg, xin, pS, W5l, b5l, out);
    }
}